// round 5
// baseline (speedup 1.0000x reference)
#include <cuda_runtime.h>
#include <cuda_bf16.h>
#include <math.h>

#define B 4
#define T 1024
#define D 512
#define U 32
#define WIDTH 64
#define EPS 1e-7f
#define TT 16                 // t-tile per block in attn kernel
#define JW 79                 // window rows per tile: TT + WIDTH - 1
#define JWP 84                // padded (multiple-of-4 loop + zero tail rows)

// Scratch: q (bh folded) and k projections, [B,T,U]
__device__ __align__(16) float g_q[B * T * U];
__device__ __align__(16) float g_k[B * T * U];

typedef unsigned long long ull;

__device__ __forceinline__ void fma2(ull& acc, ull a, ull b) {
    asm("fma.rn.f32x2 %0, %1, %2, %0;" : "+l"(acc) : "l"(a), "l"(b));
}
__device__ __forceinline__ ull add2(ull a, ull b) {
    ull r; asm("add.rn.f32x2 %0, %1, %2;" : "=l"(r) : "l"(a), "l"(b)); return r;
}
__device__ __forceinline__ ull dup2(float v) {
    ull r; asm("mov.b64 %0, {%1, %1};" : "=l"(r) : "f"(v)); return r;
}

// Padé 7/7 tanh, clamped. Max abs err ~1.1e-4, 1 MUFU.
__device__ __forceinline__ float tanh_fast(float x) {
    x = fminf(fmaxf(x, -5.0f), 5.0f);
    const float x2 = x * x;
    const float num = fmaf(fmaf(x2 + 378.0f, x2, 17325.0f), x2, 135135.0f);
    const float den = fmaf(fmaf(fmaf(28.0f, x2, 3150.0f), x2, 62370.0f), x2, 135135.0f);
    return __fdividef(x * num, den);
}

// ---------------------------------------------------------------------------
// Kernel A: q = x@Wt + bh ; k = x@Wx.
// 16 rows/block, 512 threads, grid 256, 8-way split-K over d (64 d/part).
// thread: g = tid&7 (8-u group; g<4 -> Wt, else Wx), rg = rows 2rg..2rg+1,
//         part = tid>>6. Per d: 2 LDG.128 + 8 FFMA2.
// ---------------------------------------------------------------------------
__global__ __launch_bounds__(512, 2) void qk_kernel(
    const float4* __restrict__ x4,
    const ulonglong2* __restrict__ Wt2,
    const ulonglong2* __restrict__ Wx2,
    const float4* __restrict__ bh4,
    float4* __restrict__ gq4,
    float4* __restrict__ gk4) {
    __shared__ float xs[16 * 516];                 // ~33 KB
    __shared__ ulonglong2 red[7 * 64][4];          // 28 KB split-K partials

    const int tid  = threadIdx.x;
    const int row0 = blockIdx.x * 16;

    for (int i = tid; i < 16 * 128; i += 512) {
        const int r = i >> 7, c = i & 127;
        float4 v = x4[(size_t)(row0 + r) * 128 + c];
        float* dst = &xs[r * 516 + c * 4];
        dst[0] = v.x; dst[1] = v.y; dst[2] = v.z; dst[3] = v.w;
    }
    __syncthreads();

    const int g    = tid & 7;
    const int rg   = (tid >> 3) & 7;
    const int part = tid >> 6;                     // 0..7

    // W row = 32 floats = 8 ulonglong2; group g uses 2 consecutive ull2.
    const ulonglong2* Wb = (g < 4) ? (Wt2 + g * 2) : (Wx2 + (g - 4) * 2);
    Wb += (size_t)part * 64 * 8;

    const float* x0 = &xs[(2 * rg) * 516 + part * 64];
    const float* x1 = x0 + 516;

    ull a0[4] = {0, 0, 0, 0};   // row0, u pairs
    ull a1[4] = {0, 0, 0, 0};   // row1
    #pragma unroll 4
    for (int d = 0; d < 64; d++) {
        ulonglong2 w0 = Wb[d * 8];
        ulonglong2 w1 = Wb[d * 8 + 1];
        ull xv0 = dup2(x0[d]);
        ull xv1 = dup2(x1[d]);
        fma2(a0[0], xv0, w0.x); fma2(a0[1], xv0, w0.y);
        fma2(a0[2], xv0, w1.x); fma2(a0[3], xv0, w1.y);
        fma2(a1[0], xv1, w0.x); fma2(a1[1], xv1, w0.y);
        fma2(a1[2], xv1, w1.x); fma2(a1[3], xv1, w1.y);
    }

    if (part) {
        ulonglong2* r = red[(part - 1) * 64 + (tid & 63)];
        r[0] = make_ulonglong2(a0[0], a0[1]);
        r[1] = make_ulonglong2(a0[2], a0[3]);
        r[2] = make_ulonglong2(a1[0], a1[1]);
        r[3] = make_ulonglong2(a1[2], a1[3]);
    }
    __syncthreads();

    if (part == 0) {
        #pragma unroll
        for (int p = 0; p < 7; p++) {
            const ulonglong2* r = red[p * 64 + tid];
            ulonglong2 r0 = r[0], r1 = r[1], r2 = r[2], r3 = r[3];
            a0[0] = add2(a0[0], r0.x); a0[1] = add2(a0[1], r0.y);
            a0[2] = add2(a0[2], r1.x); a0[3] = add2(a0[3], r1.y);
            a1[0] = add2(a1[0], r2.x); a1[1] = add2(a1[1], r2.y);
            a1[2] = add2(a1[2], r3.x); a1[3] = add2(a1[3], r3.y);
        }
        const int row = row0 + 2 * rg;
        float2 f[8];
        #pragma unroll
        for (int i = 0; i < 4; i++) {
            f[i]     = *reinterpret_cast<float2*>(&a0[i]);
            f[4 + i] = *reinterpret_cast<float2*>(&a1[i]);
        }
        if (g < 4) {
            float4 b0 = bh4[g * 2], b1 = bh4[g * 2 + 1];
            gq4[(size_t)row * 8 + g * 2] =
                make_float4(f[0].x + b0.x, f[0].y + b0.y, f[1].x + b0.z, f[1].y + b0.w);
            gq4[(size_t)row * 8 + g * 2 + 1] =
                make_float4(f[2].x + b1.x, f[2].y + b1.y, f[3].x + b1.z, f[3].y + b1.w);
            gq4[(size_t)(row + 1) * 8 + g * 2] =
                make_float4(f[4].x + b0.x, f[4].y + b0.y, f[5].x + b0.z, f[5].y + b0.w);
            gq4[(size_t)(row + 1) * 8 + g * 2 + 1] =
                make_float4(f[6].x + b1.x, f[6].y + b1.y, f[7].x + b1.z, f[7].y + b1.w);
        } else {
            const int gg = (g - 4) * 2;
            gk4[(size_t)row * 8 + gg] =
                make_float4(f[0].x, f[0].y, f[1].x, f[1].y);
            gk4[(size_t)row * 8 + gg + 1] =
                make_float4(f[2].x, f[2].y, f[3].x, f[3].y);
            gk4[(size_t)(row + 1) * 8 + gg] =
                make_float4(f[4].x, f[4].y, f[5].x, f[5].y);
            gk4[(size_t)(row + 1) * 8 + gg + 1] =
                make_float4(f[6].x, f[6].y, f[7].x, f[7].y);
        }
    }
}

// ---------------------------------------------------------------------------
// Kernel B: banded attention. TT=16 t's per block, 512 threads, grid 256.
// ---------------------------------------------------------------------------
__global__ __launch_bounds__(512, 2) void attn_kernel(
    const float4* __restrict__ x4,
    const float4* __restrict__ gq4,
    const float4* __restrict__ gk4,
    const float*  __restrict__ Wa,
    const float*  __restrict__ ba,
    float4* __restrict__ out4) {
    // qs/ks (phases 0/1) overlaid by e2s (phase 2, padded to JWP rows)
    __shared__ __align__(16) char ubuf[(TT * 36 + JW * 36) * 4];  // 13680 B
    __shared__ float  es[JW * 17];
    __shared__ float4 was4[8];
    __shared__ float  inv_s[TT];
    __shared__ float  ba_s;

    float*  qs  = reinterpret_cast<float*>(ubuf);   // [TT][36]
    float*  ks  = qs + TT * 36;                     // [JW][36]
    float2* e2s = reinterpret_cast<float2*>(ubuf);  // [JWP][16] = 10752 B

    const int tid   = threadIdx.x;
    const int blk   = blockIdx.x;
    const int b     = blk >> 6;
    const int t0    = (blk & 63) * TT;
    const int jbase = t0 - WIDTH / 2;

    if (tid < 8)  was4[tid] = ((const float4*)Wa)[tid];
    if (tid == 0) ba_s = ba[0];

    for (int i = tid; i < TT * 8; i += 512) {
        const int tt = i >> 3, w = i & 7;
        ((float4*)&qs[tt * 36])[w] = gq4[((size_t)(b * T + t0 + tt)) * 8 + w];
    }
    for (int i = tid; i < JW * 8; i += 512) {
        const int jj = i >> 3, w = i & 7;
        const int j = jbase + jj;
        ((float4*)&ks[jj * 36])[w] = (j >= 0 && j < T)
            ? gk4[((size_t)(b * T + j)) * 8 + w]
            : make_float4(0.f, 0.f, 0.f, 0.f);
    }
    __syncthreads();

    // phase 1: scores
    for (int idx = tid; idx < JW * TT; idx += 512) {
        const int jj = idx >> 4, tt = idx & 15;
        const int j = jbase + jj;
        float ev = 0.0f;
        if (j >= 0 && j < T && jj >= tt && jj <= tt + (WIDTH - 1)) {
            const float4* qp = (const float4*)&qs[tt * 36];
            const float4* kp = (const float4*)&ks[jj * 36];
            float s = 0.0f;
            #pragma unroll
            for (int gi = 0; gi < 8; gi++) {
                float4 q4 = qp[gi], k4 = kp[gi], w4 = was4[gi];
                s = fmaf(tanh_fast(q4.x + k4.x), w4.x, s);
                s = fmaf(tanh_fast(q4.y + k4.y), w4.y, s);
                s = fmaf(tanh_fast(q4.z + k4.z), w4.z, s);
                s = fmaf(tanh_fast(q4.w + k4.w), w4.w, s);
            }
            ev = __expf(s + ba_s);
        }
        es[jj * 17 + tt] = ev;
    }
    __syncthreads();

    if (tid < TT * 32) {
        const int w = tid >> 5, lane = tid & 31;
        float s = 0.0f;
        for (int jj = lane; jj < JW; jj += 32) s += es[jj * 17 + w];
        #pragma unroll
        for (int off = 16; off > 0; off >>= 1)
            s += __shfl_down_sync(0xffffffffu, s, off);
        if (lane == 0) inv_s[w] = __fdividef(1.0f, s + EPS);
    }
    __syncthreads();

    // normalized duplicated weights; zero tail rows [JW, JWP)
    for (int idx = tid; idx < JWP * TT; idx += 512) {
        const int jj = idx >> 4, tt = idx & 15;
        const float v = (jj < JW) ? es[jj * 17 + tt] * inv_s[tt] : 0.0f;
        e2s[jj * 16 + tt] = make_float2(v, v);
    }
    __syncthreads();

    // phase 2: v[tt][d] = sum_jj e[tt][jj] * x[jbase+jj][d], MLP=4 ring
    const int dg  = tid & 127;
    const int h   = tid >> 7;
    const int ttb = h * 4;

    const int lo = max(ttb, -jbase);
    const int hi = min(ttb + 3 + (WIDTH - 1), (T - 1) - jbase);
    const int n  = hi - lo + 1;
    const int n4 = (n + 3) & ~3;          // e2s rows [lo, lo+n4) valid (zeros past hi)

    ull acc[4][2];
    #pragma unroll
    for (int k = 0; k < 4; k++) { acc[k][0] = 0ULL; acc[k][1] = 0ULL; }

    const size_t xbase = (size_t)b * T;
    const float4* xp = x4 + (xbase + jbase + lo) * 128 + dg;
    const float2* ep = e2s + lo * 16 + ttb;

    float4 buf[4];
    #pragma unroll
    for (int p = 0; p < 4; p++)
        buf[p] = (p < n) ? xp[(size_t)p * 128] : make_float4(0.f, 0.f, 0.f, 0.f);

    #pragma unroll 4
    for (int jj = 0; jj < n4; jj++) {
        float4 xv = buf[jj & 3];
        if (jj + 4 < n) buf[jj & 3] = xp[(size_t)(jj + 4) * 128];
        ulonglong2 xpk = *reinterpret_cast<ulonglong2*>(&xv);
        ulonglong2 e01 = *reinterpret_cast<const ulonglong2*>(ep + (size_t)jj * 16);
        ulonglong2 e23 = *reinterpret_cast<const ulonglong2*>(ep + (size_t)jj * 16 + 2);
        fma2(acc[0][0], e01.x, xpk.x); fma2(acc[0][1], e01.x, xpk.y);
        fma2(acc[1][0], e01.y, xpk.x); fma2(acc[1][1], e01.y, xpk.y);
        fma2(acc[2][0], e23.x, xpk.x); fma2(acc[2][1], e23.x, xpk.y);
        fma2(acc[3][0], e23.y, xpk.x); fma2(acc[3][1], e23.y, xpk.y);
    }

    #pragma unroll
    for (int k = 0; k < 4; k++) {
        const float2 lo2 = *reinterpret_cast<float2*>(&acc[k][0]);
        const float2 hi2 = *reinterpret_cast<float2*>(&acc[k][1]);
        out4[(xbase + t0 + ttb + k) * 128 + dg] =
            make_float4(lo2.x, lo2.y, hi2.x, hi2.y);
    }
}

extern "C" void kernel_launch(void* const* d_in, const int* in_sizes, int n_in,
                              void* d_out, int out_size) {
    const float* x  = (const float*)d_in[0];
    const float* Wt = (const float*)d_in[1];
    const float* Wx = (const float*)d_in[2];
    const float* bh = (const float*)d_in[3];
    const float* Wa = (const float*)d_in[4];
    const float* ba = (const float*)d_in[5];
    float* out = (float*)d_out;

    float* gq;
    float* gk;
    cudaGetSymbolAddress((void**)&gq, g_q);
    cudaGetSymbolAddress((void**)&gk, g_k);

    qk_kernel<<<(B * T) / 16, 512>>>((const float4*)x,
                                     (const ulonglong2*)Wt,
                                     (const ulonglong2*)Wx,
                                     (const float4*)bh,
                                     (float4*)gq, (float4*)gk);
    attn_kernel<<<(B * T) / TT, 512>>>((const float4*)x,
                                       (const float4*)gq, (const float4*)gk,
                                       Wa, ba, (float4*)out);
}